// round 15
// baseline (speedup 1.0000x reference)
#include <cuda_runtime.h>
#include <cuda_fp16.h>
#include <cuda_pipeline.h>
#include <cstdint>
#include <float.h>

#define NGRAPH 1024
#define HDIM   64
#define CTAS   1024       // one CTA per graph
#define NTHR   256
#define NW     8          // warps per CTA
#define NQ     64         // quads per CTA
#define CAP    1200       // smem-cached rows per graph (mean 977, sigma 31)

// ---------------- device scratch (no allocation allowed) ----------------
__device__ float4 d_WL[32 * 256];    // packed LSTM weights: K=128 (h folded), [k4][n]
__device__ float  d_bsum[256];       // b_ih + b_hh
__device__ float4 d_W1p[32 * 256];   // W1 packed [k4][n]
__device__ float4 d_W2p[64 * 128];   // W2 packed [k4][n]
__device__ int    d_seg[NGRAPH + 1]; // segment row offsets

// dynamic shared memory (~217 KB -> occ 1)
struct Smem {
    char  cache[CAP * 128];     // fp16 rows, XOR-swizzled 16B units
    char  stage[NW][3 * 2048];  // step-0 fp32 cp.async ring (8-row slices)
    float s_rR[NQ][64];
    float s_act[128];           // [h(64) | r(64)]
    float s_c[64];
    float s_g[256];             // LSTM gates / MLP hidden
    float s_rm[NQ], s_rs[NQ], s_rmn[NQ];
    float s_h2[2];
    float s_mn, s_M;
};

// ---------------- prep: segment offsets + weight packing ----------------
__global__ void prep_kernel(const int* __restrict__ batch, int n,
                            const float* __restrict__ Wih, const float* __restrict__ Whh,
                            const float* __restrict__ bih, const float* __restrict__ bhh,
                            const float* __restrict__ W1,  const float* __restrict__ W2) {
    int t = blockIdx.x * blockDim.x + threadIdx.x;
    if (t < n) {
        int b = batch[t];
        b = min(max(b, 0), NGRAPH - 1);
        int bp;
        if (t == 0) bp = -1;
        else {
            bp = batch[t - 1];
            bp = min(max(bp, 0), NGRAPH - 1);
        }
        for (int v = bp + 1; v <= b; v++) d_seg[v] = t;
        if (t == n - 1) {
            for (int v = b + 1; v <= NGRAPH; v++) d_seg[v] = n;
        }
    }
    // gates = h @ (W_ih[:, :64] + W_hh).T + r @ W_ih[:, 64:].T + (b_ih + b_hh)
    if (t < 32 * 256) {
        int k4 = t >> 8, nn = t & 255;
        float4 w; float* wp = (float*)&w;
        #pragma unroll
        for (int j = 0; j < 4; j++) {
            int k = k4 * 4 + j;
            if (k < 64) wp[j] = Wih[nn * 128 + k] + Whh[nn * 64 + k];
            else        wp[j] = Wih[nn * 128 + k];
        }
        d_WL[t] = w;
        float4 w1; float* w1p = (float*)&w1;
        #pragma unroll
        for (int j = 0; j < 4; j++) w1p[j] = W1[nn * 128 + k4 * 4 + j];
        d_W1p[t] = w1;
    }
    if (t < 256) d_bsum[t] = bih[t] + bhh[t];
    if (t < 64 * 128) {
        int k4 = t >> 7, nn = t & 127;
        float4 w; float* wp = (float*)&w;
        #pragma unroll
        for (int j = 0; j < 4; j++) wp[j] = W2[nn * 256 + k4 * 4 + j];
        d_W2p[t] = w;
    }
}

__device__ __forceinline__ float sigmoidf_(float v) {
    return 1.0f / (1.0f + __expf(-v));
}

// fill one 8-row fp32 slice into a ring slot via cp.async
__device__ __forceinline__ void fill_slice(char* slot, const float* __restrict__ x,
                                           int srow0, int r1, int lane) {
    int row = srow0 + (lane >> 2);
    row = min(row, r1 - 1);
    const char* g = (const char*)(x + (size_t)row * HDIM) + (lane & 3) * 64;
    char* sdst = slot + (lane >> 2) * 256 + (lane & 3) * 64;
    #pragma unroll
    for (int u = 0; u < 4; u++)
        __pipeline_memcpy_async(sdst + u * 16, g + u * 16, 16);
}

__device__ __forceinline__ float dot16(const float4& v0, const float4& v1,
                                       const float4& v2, const float4& v3,
                                       const float4& q0, const float4& q1,
                                       const float4& q2, const float4& q3) {
    return v0.x * q0.x + v0.y * q0.y + v0.z * q0.z + v0.w * q0.w
         + v1.x * q1.x + v1.y * q1.y + v1.z * q1.z + v1.w * q1.w
         + v2.x * q2.x + v2.y * q2.y + v2.z * q2.z + v2.w * q2.w
         + v3.x * q3.x + v3.y * q3.y + v3.z * q3.z + v3.w * q3.w;
}

__device__ __forceinline__ void acc16(float& s, float4& R0, float4& R1, float4& R2, float4& R3,
                                      float d, const float4& v0, const float4& v1,
                                      const float4& v2, const float4& v3) {
    s += d;
    R0.x += d * v0.x; R0.y += d * v0.y; R0.z += d * v0.z; R0.w += d * v0.w;
    R1.x += d * v1.x; R1.y += d * v1.y; R1.z += d * v1.z; R1.w += d * v1.w;
    R2.x += d * v2.x; R2.y += d * v2.y; R2.z += d * v2.z; R2.w += d * v2.w;
    R3.x += d * v3.x; R3.y += d * v3.y; R3.z += d * v3.z; R3.w += d * v3.w;
}

// unpack 32B of fp16 (2 uint4) into 16 floats
__device__ __forceinline__ void unpack16(uint4 ua, uint4 ub, float4& v0, float4& v1,
                                         float4& v2, float4& v3) {
    union { uint4 u; __half2 h[4]; } pk0, pk1;
    pk0.u = ua; pk1.u = ub;
    float2 f;
    f = __half22float2(pk0.h[0]); v0.x = f.x; v0.y = f.y;
    f = __half22float2(pk0.h[1]); v0.z = f.x; v0.w = f.y;
    f = __half22float2(pk0.h[2]); v1.x = f.x; v1.y = f.y;
    f = __half22float2(pk0.h[3]); v1.z = f.x; v1.w = f.y;
    f = __half22float2(pk1.h[0]); v2.x = f.x; v2.y = f.y;
    f = __half22float2(pk1.h[1]); v2.z = f.x; v2.w = f.y;
    f = __half22float2(pk1.h[2]); v3.x = f.x; v3.y = f.y;
    f = __half22float2(pk1.h[3]); v3.z = f.x; v3.w = f.y;
}

// ---------------- fused Set2Set + MLP: 1024 CTAs x 256 thr, graph cached in smem ----------------
__global__ __launch_bounds__(NTHR, 1)
void fused_kernel(const float* __restrict__ x,
                  const float* __restrict__ b1,
                  const float* __restrict__ b2,
                  float* __restrict__ out, int n) {
    extern __shared__ char smraw[];
    Smem& S = *(Smem*)smraw;

    const int t    = threadIdx.x;
    const int g    = blockIdx.x;      // this CTA's graph
    const int w    = t >> 5;          // warp 0..7
    const int lane = t & 31;
    const int q    = lane >> 2;       // quad within warp 0..7
    const int ql   = t & 3;           // lane within quad
    const int qd   = t >> 2;          // global quad 0..63
    char* wstage   = S.stage[w];
    const unsigned qmask = 0xFu << (lane & 28);

    if (t < 128) S.s_act[t] = 0.0f;
    if (t < 64)  S.s_c[t] = 0.0f;
    if (t == 0) { S.s_mn = 0.0f; S.s_M = 0.0f; }
    int r0 = d_seg[g];
    int r1 = d_seg[g + 1];
    r0 = min(max(r0, 0), n);
    r1 = min(max(r1, r0), n);
    const int len = r1 - r0;
    const int lim = min(len, CAP);
    __syncthreads();

    for (int step = 0; step < 5; step++) {
        // ---- LSTM gates: 256 threads = 256 gates ----
        {
            float acc = d_bsum[t];
            const float4* a0 = (const float4*)S.s_act;
            #pragma unroll 8
            for (int k4 = 0; k4 < 32; k4++) {
                float4 wv = d_WL[k4 * 256 + t];
                float4 v  = a0[k4];
                acc += wv.x * v.x + wv.y * v.y + wv.z * v.z + wv.w * v.w;
            }
            S.s_g[t] = acc;
        }
        __syncthreads();
        if (t < 64) {
            float gi = sigmoidf_(S.s_g[t]);
            float gf = sigmoidf_(S.s_g[64 + t]);
            float gg = tanhf(S.s_g[128 + t]);
            float go = sigmoidf_(S.s_g[192 + t]);
            float cc = gf * S.s_c[t] + gi * gg;
            S.s_c[t] = cc;
            float hv = go * tanhf(cc);
            S.s_act[t] = hv;              // h (== q)
            float h2 = hv * hv;
            #pragma unroll
            for (int msk = 16; msk >= 1; msk >>= 1)
                h2 += __shfl_xor_sync(0xffffffffu, h2, msk);
            if (lane == 0) S.s_h2[w] = h2;
        }
        __syncthreads();
        if (t == 0)   // fixed shift: M = ||q|| * sqrt(max row-norm^2)
            S.s_M = sqrtf((S.s_h2[0] + S.s_h2[1]) * S.s_mn);
        __syncthreads();

        const float4 q0 = ((const float4*)S.s_act)[4 * ql];
        const float4 q1 = ((const float4*)S.s_act)[4 * ql + 1];
        const float4 q2 = ((const float4*)S.s_act)[4 * ql + 2];
        const float4 q3 = ((const float4*)S.s_act)[4 * ql + 3];
        const float M = S.s_M;
        float m = -FLT_MAX, s = 0.0f, mn = 0.0f;
        float4 R0 = make_float4(0.f, 0.f, 0.f, 0.f);
        float4 R1 = R0, R2 = R0, R3 = R0;

        if (step == 0) {
            // ---- step 0: stream fp32 via cp.async ring; fill smem fp16 cache ----
            constexpr int RS = 3, SLICE = 2048, STRIDE = NW * 8;   // 64 rows/step
            const int wrow0 = r0 + w * 8;
            const int iters = (r1 > wrow0) ? ((r1 - wrow0 + STRIDE - 1) / STRIDE) : 0;
            #pragma unroll
            for (int j = 0; j < RS - 1; j++) {
                if (j < iters) fill_slice(wstage + j * SLICE, x, wrow0 + j * STRIDE, r1, lane);
                __pipeline_commit();
            }
            int slot = 0;
            for (int j = 0; j < iters; j++) {
                __pipeline_wait_prior(RS - 2);
                int jn = j + RS - 1;
                int sn = slot + RS - 1; if (sn >= RS) sn -= RS;
                if (jn < iters) fill_slice(wstage + sn * SLICE, x, wrow0 + jn * STRIDE, r1, lane);
                __pipeline_commit();
                // consume row wrow0 + j*STRIDE + q
                {
                    const int row = wrow0 + j * STRIDE + q;
                    const int lr  = row - r0;
                    const bool act = (row < r1);
                    const float4* p4 = (const float4*)(wstage + slot * SLICE + q * 256 + ql * 64);
                    float4 v0 = p4[0], v1 = p4[1], v2 = p4[2], v3 = p4[3];
                    if (act && lr < CAP) {   // fp16 copy into smem cache (swizzled)
                        union { uint4 u; __half2 h[4]; } pk0, pk1;
                        pk0.h[0] = __floats2half2_rn(v0.x, v0.y);
                        pk0.h[1] = __floats2half2_rn(v0.z, v0.w);
                        pk0.h[2] = __floats2half2_rn(v1.x, v1.y);
                        pk0.h[3] = __floats2half2_rn(v1.z, v1.w);
                        pk1.h[0] = __floats2half2_rn(v2.x, v2.y);
                        pk1.h[1] = __floats2half2_rn(v2.z, v2.w);
                        pk1.h[2] = __floats2half2_rn(v3.x, v3.y);
                        pk1.h[3] = __floats2half2_rn(v3.z, v3.w);
                        char* cb = S.cache + lr * 128;
                        *(uint4*)(cb + (((2 * ql)     ^ (lr & 7)) * 16)) = pk0.u;
                        *(uint4*)(cb + (((2 * ql + 1) ^ (lr & 7)) * 16)) = pk1.u;
                    }
                    float p  = dot16(v0, v1, v2, v3, q0, q1, q2, q3);
                    float n2 = dot16(v0, v1, v2, v3, v0, v1, v2, v3);
                    p  += __shfl_xor_sync(0xffffffffu, p, 1);
                    n2 += __shfl_xor_sync(0xffffffffu, n2, 1);
                    p  += __shfl_xor_sync(0xffffffffu, p, 2);
                    n2 += __shfl_xor_sync(0xffffffffu, n2, 2);
                    if (act) {
                        mn = fmaxf(mn, n2);
                        if (p > m) {
                            float sc = __expf(m - p);
                            s *= sc;
                            R0.x *= sc; R0.y *= sc; R0.z *= sc; R0.w *= sc;
                            R1.x *= sc; R1.y *= sc; R1.z *= sc; R1.w *= sc;
                            R2.x *= sc; R2.y *= sc; R2.z *= sc; R2.w *= sc;
                            R3.x *= sc; R3.y *= sc; R3.z *= sc; R3.w *= sc;
                            m = p;
                        }
                        float d = __expf(p - m);
                        acc16(s, R0, R1, R2, R3, d, v0, v1, v2, v3);
                    }
                }
                __syncwarp();
                slot++; if (slot == RS) slot = 0;
            }
            __pipeline_wait_prior(0);
        } else {
            // ---- steps 1-4: consume from smem cache, batch-2 rows ----
            for (int base = w * 8; base < lim; base += 128) {
                int lrA = base + q, lrB = base + 64 + q;
                bool aA = (lrA < lim), aB = (lrB < lim);
                int cA = min(lrA, lim - 1), cB = min(lrB, lim - 1);
                const char* ba = S.cache + cA * 128;
                const char* bb = S.cache + cB * 128;
                uint4 ua0 = *(const uint4*)(ba + (((2 * ql)     ^ (cA & 7)) * 16));
                uint4 ua1 = *(const uint4*)(ba + (((2 * ql + 1) ^ (cA & 7)) * 16));
                uint4 ub0 = *(const uint4*)(bb + (((2 * ql)     ^ (cB & 7)) * 16));
                uint4 ub1 = *(const uint4*)(bb + (((2 * ql + 1) ^ (cB & 7)) * 16));
                float4 a0, a1, a2, a3, b0, b1_, b2_, b3;
                unpack16(ua0, ua1, a0, a1, a2, a3);
                unpack16(ub0, ub1, b0, b1_, b2_, b3);
                float pA = dot16(a0, a1, a2, a3, q0, q1, q2, q3);
                float pB = dot16(b0, b1_, b2_, b3, q0, q1, q2, q3);
                pA += __shfl_xor_sync(0xffffffffu, pA, 1);
                pB += __shfl_xor_sync(0xffffffffu, pB, 1);
                pA += __shfl_xor_sync(0xffffffffu, pA, 2);
                pB += __shfl_xor_sync(0xffffffffu, pB, 2);
                float dA = aA ? __expf(pA - M) : 0.0f;
                float dB = aB ? __expf(pB - M) : 0.0f;
                acc16(s, R0, R1, R2, R3, dA, a0, a1, a2, a3);
                acc16(s, R0, R1, R2, R3, dB, b0, b1_, b2_, b3);
            }
            // overflow rows (normally none): direct fp32 reads
            for (int row = r0 + CAP + w * 8 + q; row < r1; row += NW * 8) {
                const float4* rp = (const float4*)(x + (size_t)row * HDIM) + 4 * ql;
                float4 v0 = __ldg(rp), v1 = __ldg(rp + 1), v2 = __ldg(rp + 2), v3 = __ldg(rp + 3);
                float p = dot16(v0, v1, v2, v3, q0, q1, q2, q3);
                p += __shfl_xor_sync(qmask, p, 1);
                p += __shfl_xor_sync(qmask, p, 2);
                float d = __expf(p - M);
                acc16(s, R0, R1, R2, R3, d, v0, v1, v2, v3);
            }
        }

        // ---- combine NQ quad partials ----
        if (ql == 0) {
            S.s_rm[qd]  = (step == 0) ? m : M;
            S.s_rs[qd]  = s;
            S.s_rmn[qd] = mn;
        }
        ((float4*)S.s_rR[qd])[4 * ql]     = R0;
        ((float4*)S.s_rR[qd])[4 * ql + 1] = R1;
        ((float4*)S.s_rR[qd])[4 * ql + 2] = R2;
        ((float4*)S.s_rR[qd])[4 * ql + 3] = R3;
        __syncthreads();
        if (t < 64) {
            float Mx = -FLT_MAX;
            #pragma unroll 16
            for (int p = 0; p < NQ; p++) Mx = fmaxf(Mx, S.s_rm[p]);
            float st = 0.0f, Rk = 0.0f;
            #pragma unroll 16
            for (int p = 0; p < NQ; p++) {
                float wq = __expf(S.s_rm[p] - Mx);
                st += wq * S.s_rs[p];
                Rk += wq * S.s_rR[p][t];
            }
            S.s_act[64 + t] = Rk / fmaxf(st, 1e-16f);   // r
            if (step == 0 && t == 0) {
                float mnx = 0.0f;
                #pragma unroll 16
                for (int p = 0; p < NQ; p++) mnx = fmaxf(mnx, S.s_rmn[p]);
                S.s_mn = mnx;
            }
        }
        __syncthreads();
    }

    // ---- final MLP: 128 -> 256 (relu) -> 128 ----
    {
        float acc = b1[t];
        const float4* a = (const float4*)S.s_act;
        #pragma unroll 8
        for (int k4 = 0; k4 < 32; k4++) {
            float4 wv = d_W1p[k4 * 256 + t];
            float4 v  = a[k4];
            acc += wv.x * v.x + wv.y * v.y + wv.z * v.z + wv.w * v.w;
        }
        S.s_g[t] = fmaxf(acc, 0.0f);
    }
    __syncthreads();
    if (t < 128) {
        float acc = b2[t];
        const float4* hv = (const float4*)S.s_g;
        #pragma unroll 8
        for (int k4 = 0; k4 < 64; k4++) {
            float4 wv = d_W2p[k4 * 128 + t];
            float4 v  = hv[k4];
            acc += wv.x * v.x + wv.y * v.y + wv.z * v.z + wv.w * v.w;
        }
        out[(size_t)g * 128 + t] = acc;
    }
}

extern "C" void kernel_launch(void* const* d_in, const int* in_sizes, int n_in,
                              void* d_out, int out_size) {
    const float* x     = (const float*)d_in[0];
    const int*   batch = (const int*)d_in[1];     // int32 (JAX x64 disabled)
    const float* Wih   = (const float*)d_in[2];
    const float* Whh   = (const float*)d_in[3];
    const float* bih   = (const float*)d_in[4];
    const float* bhh   = (const float*)d_in[5];
    const float* W1    = (const float*)d_in[6];
    const float* b1    = (const float*)d_in[7];
    const float* W2    = (const float*)d_in[8];
    const float* b2    = (const float*)d_in[9];

    int n = in_sizes[0] / HDIM;   // number of nodes

    static_assert(sizeof(Smem) <= 227 * 1024, "smem exceeds per-CTA limit");
    cudaFuncSetAttribute(fused_kernel, cudaFuncAttributeMaxDynamicSharedMemorySize,
                         (int)sizeof(Smem));

    prep_kernel<<<(n + 511) / 512, 512>>>(batch, n, Wih, Whh, bih, bhh, W1, W2);
    fused_kernel<<<CTAS, NTHR, sizeof(Smem)>>>(x, b1, b2, (float*)d_out, n);
}

// round 16
// speedup vs baseline: 1.1338x; 1.1338x over previous
#include <cuda_runtime.h>
#include <cuda_fp16.h>
#include <cuda_pipeline.h>
#include <cstdint>
#include <float.h>

#define NGRAPH 1024
#define HDIM   64
#define NMAX   1000000
#define CTAS   1024       // one CTA per graph
#define NTHR   256
#define NW     8          // warps per CTA
#define NQ     64         // quads per CTA
#define CAP    624        // smem-cached rows per graph (mean 977) -> ~64%

// ---------------- device scratch (no allocation allowed) ----------------
__device__ float4 d_WL[32 * 256];    // packed LSTM weights: K=128 (h folded), [k4][n]
__device__ float  d_bsum[256];       // b_ih + b_hh
__device__ float4 d_W1p[32 * 256];   // W1 packed [k4][n]
__device__ float4 d_W2p[64 * 128];   // W2 packed [k4][n]
__device__ int    d_seg[NGRAPH + 1]; // segment row offsets
__device__ uint4  d_xh[NMAX * 8];    // fp16 overflow rows (only lr >= CAP used)

// dynamic shared memory (~112.5 KB -> 2 CTAs/SM = 16 warps)
struct Smem {
    char cache[CAP * 128];           // fp16 rows, XOR-swizzled 16B units
    union {
        char  stage[NW][4096];       // step-0 fp32 ring: 2 slots x 2KB (8 rows)
        float s_rR[NQ][64];          // combine scratch (stage dead by then)
    } u;
    float s_act[128];                // [h(64) | r(64)]
    float s_c[64];
    float s_g[256];                  // LSTM gates / MLP hidden
    float s_rm[NQ], s_rs[NQ], s_rmn[NQ];
    float s_h2[NW];
    float s_mn, s_M;
};

// ---------------- prep: segment offsets + weight packing ----------------
__global__ void prep_kernel(const int* __restrict__ batch, int n,
                            const float* __restrict__ Wih, const float* __restrict__ Whh,
                            const float* __restrict__ bih, const float* __restrict__ bhh,
                            const float* __restrict__ W1,  const float* __restrict__ W2) {
    int t = blockIdx.x * blockDim.x + threadIdx.x;
    if (t < n) {
        int b = batch[t];
        b = min(max(b, 0), NGRAPH - 1);
        int bp;
        if (t == 0) bp = -1;
        else {
            bp = batch[t - 1];
            bp = min(max(bp, 0), NGRAPH - 1);
        }
        for (int v = bp + 1; v <= b; v++) d_seg[v] = t;
        if (t == n - 1) {
            for (int v = b + 1; v <= NGRAPH; v++) d_seg[v] = n;
        }
    }
    // gates = h @ (W_ih[:, :64] + W_hh).T + r @ W_ih[:, 64:].T + (b_ih + b_hh)
    if (t < 32 * 256) {
        int k4 = t >> 8, nn = t & 255;
        float4 w; float* wp = (float*)&w;
        #pragma unroll
        for (int j = 0; j < 4; j++) {
            int k = k4 * 4 + j;
            if (k < 64) wp[j] = Wih[nn * 128 + k] + Whh[nn * 64 + k];
            else        wp[j] = Wih[nn * 128 + k];
        }
        d_WL[t] = w;
        float4 w1; float* w1p = (float*)&w1;
        #pragma unroll
        for (int j = 0; j < 4; j++) w1p[j] = W1[nn * 128 + k4 * 4 + j];
        d_W1p[t] = w1;
    }
    if (t < 256) d_bsum[t] = bih[t] + bhh[t];
    if (t < 64 * 128) {
        int k4 = t >> 7, nn = t & 127;
        float4 w; float* wp = (float*)&w;
        #pragma unroll
        for (int j = 0; j < 4; j++) wp[j] = W2[nn * 256 + k4 * 4 + j];
        d_W2p[t] = w;
    }
}

__device__ __forceinline__ float sigmoidf_(float v) {
    return 1.0f / (1.0f + __expf(-v));
}

// fill one 8-row fp32 slice into a ring slot via cp.async
__device__ __forceinline__ void fill_slice(char* slot, const float* __restrict__ x,
                                           int srow0, int r1, int lane) {
    int row = srow0 + (lane >> 2);
    row = min(row, r1 - 1);
    const char* g = (const char*)(x + (size_t)row * HDIM) + (lane & 3) * 64;
    char* sdst = slot + (lane >> 2) * 256 + (lane & 3) * 64;
    #pragma unroll
    for (int u = 0; u < 4; u++)
        __pipeline_memcpy_async(sdst + u * 16, g + u * 16, 16);
}

__device__ __forceinline__ float dot16(const float4& v0, const float4& v1,
                                       const float4& v2, const float4& v3,
                                       const float4& q0, const float4& q1,
                                       const float4& q2, const float4& q3) {
    return v0.x * q0.x + v0.y * q0.y + v0.z * q0.z + v0.w * q0.w
         + v1.x * q1.x + v1.y * q1.y + v1.z * q1.z + v1.w * q1.w
         + v2.x * q2.x + v2.y * q2.y + v2.z * q2.z + v2.w * q2.w
         + v3.x * q3.x + v3.y * q3.y + v3.z * q3.z + v3.w * q3.w;
}

__device__ __forceinline__ void acc16(float& s, float4& R0, float4& R1, float4& R2, float4& R3,
                                      float d, const float4& v0, const float4& v1,
                                      const float4& v2, const float4& v3) {
    s += d;
    R0.x += d * v0.x; R0.y += d * v0.y; R0.z += d * v0.z; R0.w += d * v0.w;
    R1.x += d * v1.x; R1.y += d * v1.y; R1.z += d * v1.z; R1.w += d * v1.w;
    R2.x += d * v2.x; R2.y += d * v2.y; R2.z += d * v2.z; R2.w += d * v2.w;
    R3.x += d * v3.x; R3.y += d * v3.y; R3.z += d * v3.z; R3.w += d * v3.w;
}

// unpack 32B of fp16 (2 uint4) into 16 floats
__device__ __forceinline__ void unpack16(uint4 ua, uint4 ub, float4& v0, float4& v1,
                                         float4& v2, float4& v3) {
    union { uint4 u; __half2 h[4]; } pk0, pk1;
    pk0.u = ua; pk1.u = ub;
    float2 f;
    f = __half22float2(pk0.h[0]); v0.x = f.x; v0.y = f.y;
    f = __half22float2(pk0.h[1]); v0.z = f.x; v0.w = f.y;
    f = __half22float2(pk0.h[2]); v1.x = f.x; v1.y = f.y;
    f = __half22float2(pk0.h[3]); v1.z = f.x; v1.w = f.y;
    f = __half22float2(pk1.h[0]); v2.x = f.x; v2.y = f.y;
    f = __half22float2(pk1.h[1]); v2.z = f.x; v2.w = f.y;
    f = __half22float2(pk1.h[2]); v3.x = f.x; v3.y = f.y;
    f = __half22float2(pk1.h[3]); v3.z = f.x; v3.w = f.y;
}

__device__ __forceinline__ uint4 pack8(const float4& a, const float4& b) {
    union { uint4 u; __half2 h[4]; } pk;
    pk.h[0] = __floats2half2_rn(a.x, a.y);
    pk.h[1] = __floats2half2_rn(a.z, a.w);
    pk.h[2] = __floats2half2_rn(b.x, b.y);
    pk.h[3] = __floats2half2_rn(b.z, b.w);
    return pk.u;
}

// ---------------- fused Set2Set + MLP: 1024 CTAs x 256 thr, occ 2, smem row cache ----------------
__global__ __launch_bounds__(NTHR, 2)
void fused_kernel(const float* __restrict__ x,
                  const float* __restrict__ b1,
                  const float* __restrict__ b2,
                  float* __restrict__ out, int n) {
    extern __shared__ char smraw[];
    Smem& S = *(Smem*)smraw;

    const int t    = threadIdx.x;
    const int g    = blockIdx.x;      // this CTA's graph
    const int w    = t >> 5;          // warp 0..7
    const int lane = t & 31;
    const int q    = lane >> 2;       // quad within warp 0..7
    const int ql   = t & 3;           // lane within quad
    const int qd   = t >> 2;          // global quad 0..63

    if (t < 128) S.s_act[t] = 0.0f;
    if (t < 64)  S.s_c[t] = 0.0f;
    if (t == 0) { S.s_mn = 0.0f; S.s_M = 0.0f; }
    int r0 = d_seg[g];
    int r1 = d_seg[g + 1];
    r0 = min(max(r0, 0), n);
    r1 = min(max(r1, r0), n);
    const int len = r1 - r0;
    const int lim = min(len, CAP);
    __syncthreads();

    for (int step = 0; step < 5; step++) {
        // ---- LSTM gates: 256 threads = 256 gates ----
        {
            float acc = d_bsum[t];
            const float4* a0 = (const float4*)S.s_act;
            #pragma unroll 8
            for (int k4 = 0; k4 < 32; k4++) {
                float4 wv = d_WL[k4 * 256 + t];
                float4 v  = a0[k4];
                acc += wv.x * v.x + wv.y * v.y + wv.z * v.z + wv.w * v.w;
            }
            S.s_g[t] = acc;
        }
        __syncthreads();
        if (t < 64) {
            float gi = sigmoidf_(S.s_g[t]);
            float gf = sigmoidf_(S.s_g[64 + t]);
            float gg = tanhf(S.s_g[128 + t]);
            float go = sigmoidf_(S.s_g[192 + t]);
            float cc = gf * S.s_c[t] + gi * gg;
            S.s_c[t] = cc;
            float hv = go * tanhf(cc);
            S.s_act[t] = hv;              // h (== q)
            float h2 = hv * hv;
            #pragma unroll
            for (int msk = 16; msk >= 1; msk >>= 1)
                h2 += __shfl_xor_sync(0xffffffffu, h2, msk);
            if (lane == 0) S.s_h2[w] = h2;
        }
        __syncthreads();
        if (t == 0)   // fixed shift: M = ||q|| * sqrt(max row-norm^2)
            S.s_M = sqrtf((S.s_h2[0] + S.s_h2[1]) * S.s_mn);
        __syncthreads();

        const float4 q0 = ((const float4*)S.s_act)[4 * ql];
        const float4 q1 = ((const float4*)S.s_act)[4 * ql + 1];
        const float4 q2 = ((const float4*)S.s_act)[4 * ql + 2];
        const float4 q3 = ((const float4*)S.s_act)[4 * ql + 3];
        const float M = S.s_M;
        float m = -FLT_MAX, s = 0.0f, mn = 0.0f;
        float4 R0 = make_float4(0.f, 0.f, 0.f, 0.f);
        float4 R1 = R0, R2 = R0, R3 = R0;

        if (step == 0) {
            // ---- step 0: stream all rows fp32 via cp.async double buffer ----
            constexpr int SLICE = 2048, STRIDE = NW * 8;   // 64 rows per ring step
            char* wstage = S.u.stage[w];
            const int wrow0 = r0 + w * 8;
            const int iters = (r1 > wrow0) ? ((r1 - wrow0 + STRIDE - 1) / STRIDE) : 0;
            if (iters > 0) fill_slice(wstage, x, wrow0, r1, lane);
            __pipeline_commit();
            for (int j = 0; j < iters; j++) {
                int slot = j & 1;
                if (j + 1 < iters)
                    fill_slice(wstage + (slot ^ 1) * SLICE, x, wrow0 + (j + 1) * STRIDE, r1, lane);
                __pipeline_commit();
                __pipeline_wait_prior(1);    // slice j ready
                {
                    const int row = wrow0 + j * STRIDE + q;
                    const int lr  = row - r0;
                    const bool act = (row < r1);
                    const float4* p4 = (const float4*)(wstage + slot * SLICE + q * 256 + ql * 64);
                    float4 v0 = p4[0], v1 = p4[1], v2 = p4[2], v3 = p4[3];
                    if (act) {
                        uint4 u0 = pack8(v0, v1);
                        uint4 u1 = pack8(v2, v3);
                        if (lr < CAP) {      // smem cache, XOR-swizzled 16B units
                            char* cb = S.cache + lr * 128;
                            *(uint4*)(cb + (((2 * ql)     ^ (lr & 7)) * 16)) = u0;
                            *(uint4*)(cb + (((2 * ql + 1) ^ (lr & 7)) * 16)) = u1;
                        } else {             // global overflow (L2-resident, ~46MB total)
                            d_xh[(size_t)row * 8 + 2 * ql]     = u0;
                            d_xh[(size_t)row * 8 + 2 * ql + 1] = u1;
                        }
                    }
                    float p  = dot16(v0, v1, v2, v3, q0, q1, q2, q3);
                    float n2 = dot16(v0, v1, v2, v3, v0, v1, v2, v3);
                    p  += __shfl_xor_sync(0xffffffffu, p, 1);
                    n2 += __shfl_xor_sync(0xffffffffu, n2, 1);
                    p  += __shfl_xor_sync(0xffffffffu, p, 2);
                    n2 += __shfl_xor_sync(0xffffffffu, n2, 2);
                    if (act) {
                        mn = fmaxf(mn, n2);
                        if (p > m) {
                            float sc = __expf(m - p);
                            s *= sc;
                            R0.x *= sc; R0.y *= sc; R0.z *= sc; R0.w *= sc;
                            R1.x *= sc; R1.y *= sc; R1.z *= sc; R1.w *= sc;
                            R2.x *= sc; R2.y *= sc; R2.z *= sc; R2.w *= sc;
                            R3.x *= sc; R3.y *= sc; R3.z *= sc; R3.w *= sc;
                            m = p;
                        }
                        acc16(s, R0, R1, R2, R3, __expf(p - m), v0, v1, v2, v3);
                    }
                }
                __syncwarp();
                slot ^= 1;
            }
            __pipeline_wait_prior(0);
            __syncthreads();   // ALL warps done with stage before s_rR (union) is written
        } else {
            // ---- steps 1-4: smem cache (batch-2 rows per quad), then global overflow ----
            for (int base = w * 16; base < lim; base += 128) {
                int lrA = base + q, lrB = base + 8 + q;
                bool aA = (lrA < lim), aB = (lrB < lim);
                int cA = min(lrA, lim - 1), cB = min(lrB, lim - 1);
                const char* ba = S.cache + cA * 128;
                const char* bb = S.cache + cB * 128;
                uint4 ua0 = *(const uint4*)(ba + (((2 * ql)     ^ (cA & 7)) * 16));
                uint4 ua1 = *(const uint4*)(ba + (((2 * ql + 1) ^ (cA & 7)) * 16));
                uint4 ub0 = *(const uint4*)(bb + (((2 * ql)     ^ (cB & 7)) * 16));
                uint4 ub1 = *(const uint4*)(bb + (((2 * ql + 1) ^ (cB & 7)) * 16));
                float4 a0, a1, a2, a3, b0, b1_, b2_, b3;
                unpack16(ua0, ua1, a0, a1, a2, a3);
                unpack16(ub0, ub1, b0, b1_, b2_, b3);
                float pA = dot16(a0, a1, a2, a3, q0, q1, q2, q3);
                float pB = dot16(b0, b1_, b2_, b3, q0, q1, q2, q3);
                pA += __shfl_xor_sync(0xffffffffu, pA, 1);
                pB += __shfl_xor_sync(0xffffffffu, pB, 1);
                pA += __shfl_xor_sync(0xffffffffu, pA, 2);
                pB += __shfl_xor_sync(0xffffffffu, pB, 2);
                float dA = aA ? __expf(pA - M) : 0.0f;
                float dB = aB ? __expf(pB - M) : 0.0f;
                acc16(s, R0, R1, R2, R3, dA, a0, a1, a2, a3);
                acc16(s, R0, R1, R2, R3, dB, b0, b1_, b2_, b3);
            }
            // overflow rows from global fp16 (warp-uniform trip count; per-quad masking)
            for (int o = r0 + CAP + w * 8; o < r1; o += NW * 8) {
                int row = o + q;
                bool act = (row < r1);
                int cr = min(row, r1 - 1);
                uint4 u0 = __ldg(&d_xh[(size_t)cr * 8 + 2 * ql]);
                uint4 u1 = __ldg(&d_xh[(size_t)cr * 8 + 2 * ql + 1]);
                float4 v0, v1, v2, v3;
                unpack16(u0, u1, v0, v1, v2, v3);
                float p = dot16(v0, v1, v2, v3, q0, q1, q2, q3);
                p += __shfl_xor_sync(0xffffffffu, p, 1);
                p += __shfl_xor_sync(0xffffffffu, p, 2);
                float d = act ? __expf(p - M) : 0.0f;
                acc16(s, R0, R1, R2, R3, d, v0, v1, v2, v3);
            }
        }

        // ---- combine NQ quad partials (u.s_rR aliases the now-dead stage) ----
        if (ql == 0) {
            S.s_rm[qd]  = (step == 0) ? m : M;
            S.s_rs[qd]  = s;
            S.s_rmn[qd] = mn;
        }
        ((float4*)S.u.s_rR[qd])[4 * ql]     = R0;
        ((float4*)S.u.s_rR[qd])[4 * ql + 1] = R1;
        ((float4*)S.u.s_rR[qd])[4 * ql + 2] = R2;
        ((float4*)S.u.s_rR[qd])[4 * ql + 3] = R3;
        __syncthreads();
        if (t < 64) {
            float Mx = -FLT_MAX;
            #pragma unroll 16
            for (int p = 0; p < NQ; p++) Mx = fmaxf(Mx, S.s_rm[p]);
            float st = 0.0f, Rk = 0.0f;
            #pragma unroll 16
            for (int p = 0; p < NQ; p++) {
                float wq = __expf(S.s_rm[p] - Mx);
                st += wq * S.s_rs[p];
                Rk += wq * S.u.s_rR[p][t];
            }
            S.s_act[64 + t] = Rk / fmaxf(st, 1e-16f);   // r
            if (step == 0 && t == 0) {
                float mnx = 0.0f;
                #pragma unroll 16
                for (int p = 0; p < NQ; p++) mnx = fmaxf(mnx, S.s_rmn[p]);
                S.s_mn = mnx;
            }
        }
        __syncthreads();
    }

    // ---- final MLP: 128 -> 256 (relu) -> 128 ----
    {
        float acc = b1[t];
        const float4* a = (const float4*)S.s_act;
        #pragma unroll 8
        for (int k4 = 0; k4 < 32; k4++) {
            float4 wv = d_W1p[k4 * 256 + t];
            float4 v  = a[k4];
            acc += wv.x * v.x + wv.y * v.y + wv.z * v.z + wv.w * v.w;
        }
        S.s_g[t] = fmaxf(acc, 0.0f);
    }
    __syncthreads();
    if (t < 128) {
        float acc = b2[t];
        const float4* hv = (const float4*)S.s_g;
        #pragma unroll 8
        for (int k4 = 0; k4 < 64; k4++) {
            float4 wv = d_W2p[k4 * 128 + t];
            float4 v  = hv[k4];
            acc += wv.x * v.x + wv.y * v.y + wv.z * v.z + wv.w * v.w;
        }
        out[(size_t)g * 128 + t] = acc;
    }
}

extern "C" void kernel_launch(void* const* d_in, const int* in_sizes, int n_in,
                              void* d_out, int out_size) {
    const float* x     = (const float*)d_in[0];
    const int*   batch = (const int*)d_in[1];     // int32 (JAX x64 disabled)
    const float* Wih   = (const float*)d_in[2];
    const float* Whh   = (const float*)d_in[3];
    const float* bih   = (const float*)d_in[4];
    const float* bhh   = (const float*)d_in[5];
    const float* W1    = (const float*)d_in[6];
    const float* b1    = (const float*)d_in[7];
    const float* W2    = (const float*)d_in[8];
    const float* b2    = (const float*)d_in[9];

    int n = in_sizes[0] / HDIM;   // number of nodes

    static_assert(sizeof(Smem) <= 115300, "smem too big for occ 2");
    cudaFuncSetAttribute(fused_kernel, cudaFuncAttributeMaxDynamicSharedMemorySize,
                         (int)sizeof(Smem));

    prep_kernel<<<(n + 511) / 512, 512>>>(batch, n, Wih, Whh, bih, bhh, W1, W2);
    fused_kernel<<<CTAS, NTHR, sizeof(Smem)>>>(x, b1, b2, (float*)d_out, n);
}

// round 17
// speedup vs baseline: 1.2068x; 1.0644x over previous
#include <cuda_runtime.h>
#include <cuda_fp16.h>
#include <cuda_pipeline.h>
#include <cstdint>
#include <float.h>

#define NGRAPH 1024
#define HDIM   64
#define NMAX   1000000
#define CTAS   1024       // one CTA per graph
#define NTHR   64
#define NW     2          // warps per CTA
#define NQ     16         // quads per CTA

// ---------------- device scratch (no allocation allowed) ----------------
__device__ float4 d_WL[32 * 256];    // packed LSTM weights: K=128 (h folded), [k4][n]
__device__ float  d_bsum[256];       // b_ih + b_hh
__device__ float4 d_W1p[32 * 256];   // W1 packed [k4][n]
__device__ float4 d_W2p[64 * 128];   // W2 packed [k4][n]
__device__ int    d_seg[NGRAPH + 1]; // segment row offsets
__device__ uint4  d_xh[NMAX * 8];    // fp16 copy of x (row = 64 halves = 8 uint4)
// inter-kernel state
__device__ float  d_sh[NGRAPH * 64];
__device__ float  d_sc[NGRAPH * 64];
__device__ float  d_sr[NGRAPH * 64];
__device__ float  d_smn[NGRAPH];

// ---------------- prep: segment offsets + weight packing ----------------
__global__ void prep_kernel(const int* __restrict__ batch, int n,
                            const float* __restrict__ Wih, const float* __restrict__ Whh,
                            const float* __restrict__ bih, const float* __restrict__ bhh,
                            const float* __restrict__ W1,  const float* __restrict__ W2) {
    int t = blockIdx.x * blockDim.x + threadIdx.x;
    if (t < n) {
        int b = batch[t];
        b = min(max(b, 0), NGRAPH - 1);
        int bp;
        if (t == 0) bp = -1;
        else {
            bp = batch[t - 1];
            bp = min(max(bp, 0), NGRAPH - 1);
        }
        for (int v = bp + 1; v <= b; v++) d_seg[v] = t;
        if (t == n - 1) {
            for (int v = b + 1; v <= NGRAPH; v++) d_seg[v] = n;
        }
    }
    // gates = h @ (W_ih[:, :64] + W_hh).T + r @ W_ih[:, 64:].T + (b_ih + b_hh)
    if (t < 32 * 256) {
        int k4 = t >> 8, nn = t & 255;
        float4 w; float* wp = (float*)&w;
        #pragma unroll
        for (int j = 0; j < 4; j++) {
            int k = k4 * 4 + j;
            if (k < 64) wp[j] = Wih[nn * 128 + k] + Whh[nn * 64 + k];
            else        wp[j] = Wih[nn * 128 + k];
        }
        d_WL[t] = w;
        float4 w1; float* w1p = (float*)&w1;
        #pragma unroll
        for (int j = 0; j < 4; j++) w1p[j] = W1[nn * 128 + k4 * 4 + j];
        d_W1p[t] = w1;
    }
    if (t < 256) d_bsum[t] = bih[t] + bhh[t];
    if (t < 64 * 128) {
        int k4 = t >> 7, nn = t & 127;
        float4 w; float* wp = (float*)&w;
        #pragma unroll
        for (int j = 0; j < 4; j++) wp[j] = W2[nn * 256 + k4 * 4 + j];
        d_W2p[t] = w;
    }
}

__device__ __forceinline__ float sigmoidf_(float v) {
    return 1.0f / (1.0f + __expf(-v));
}

__device__ __forceinline__ float dot16(const float4& v0, const float4& v1,
                                       const float4& v2, const float4& v3,
                                       const float4& q0, const float4& q1,
                                       const float4& q2, const float4& q3) {
    return v0.x * q0.x + v0.y * q0.y + v0.z * q0.z + v0.w * q0.w
         + v1.x * q1.x + v1.y * q1.y + v1.z * q1.z + v1.w * q1.w
         + v2.x * q2.x + v2.y * q2.y + v2.z * q2.z + v2.w * q2.w
         + v3.x * q3.x + v3.y * q3.y + v3.z * q3.z + v3.w * q3.w;
}

__device__ __forceinline__ void acc16(float& s, float4& R0, float4& R1, float4& R2, float4& R3,
                                      float d, const float4& v0, const float4& v1,
                                      const float4& v2, const float4& v3) {
    s += d;
    R0.x += d * v0.x; R0.y += d * v0.y; R0.z += d * v0.z; R0.w += d * v0.w;
    R1.x += d * v1.x; R1.y += d * v1.y; R1.z += d * v1.z; R1.w += d * v1.w;
    R2.x += d * v2.x; R2.y += d * v2.y; R2.z += d * v2.z; R2.w += d * v2.w;
    R3.x += d * v3.x; R3.y += d * v3.y; R3.z += d * v3.z; R3.w += d * v3.w;
}

// ================= K0: step 0 — fp32 stream + fp16 copy + online softmax =================
struct SmemK0 {
    char  stage[NW][3 * 2048];  // fp32 ring: 3 slots x 8 rows
    float s_rR[NQ][64];
    float s_act[64];            // h1 (== q)
    float s_rm[NQ], s_rs[NQ], s_rmn[NQ];
};

__device__ __forceinline__ void fill32(char* slot, const float* __restrict__ x,
                                       int srow0, int r1, int lane) {
    int row = srow0 + (lane >> 2);
    row = min(row, r1 - 1);
    const char* g = (const char*)(x + (size_t)row * HDIM) + (lane & 3) * 64;
    char* sdst = slot + (lane >> 2) * 256 + (lane & 3) * 64;
    #pragma unroll
    for (int u = 0; u < 4; u++)
        __pipeline_memcpy_async(sdst + u * 16, g + u * 16, 16);
}

__global__ __launch_bounds__(NTHR, 8)
void step0_kernel(const float* __restrict__ x, int n) {
    extern __shared__ char smraw[];
    SmemK0& S = *(SmemK0*)smraw;

    const int t    = threadIdx.x;
    const int g    = blockIdx.x;
    const int w    = t >> 5;
    const int lane = t & 31;
    const int q    = lane >> 2;
    const int ql   = t & 3;
    const int qd   = t >> 2;

    // step-0 LSTM input is all zero -> gates = bias
    {
        float gi = sigmoidf_(d_bsum[t]);
        float gf = sigmoidf_(d_bsum[64 + t]);   (void)gf;  // c_prev = 0
        float gg = tanhf(d_bsum[128 + t]);
        float go = sigmoidf_(d_bsum[192 + t]);
        float cc = gi * gg;
        float hv = go * tanhf(cc);
        S.s_act[t] = hv;
        d_sh[g * 64 + t] = hv;
        d_sc[g * 64 + t] = cc;
    }
    int r0 = d_seg[g];
    int r1 = d_seg[g + 1];
    r0 = min(max(r0, 0), n);
    r1 = min(max(r1, r0), n);
    __syncthreads();

    const float4 q0 = ((const float4*)S.s_act)[4 * ql];
    const float4 q1 = ((const float4*)S.s_act)[4 * ql + 1];
    const float4 q2 = ((const float4*)S.s_act)[4 * ql + 2];
    const float4 q3 = ((const float4*)S.s_act)[4 * ql + 3];
    float m = -FLT_MAX, s = 0.0f, mn = 0.0f;
    float4 R0 = make_float4(0.f, 0.f, 0.f, 0.f);
    float4 R1 = R0, R2 = R0, R3 = R0;

    {
        constexpr int RS = 3, SLICE = 2048, STRIDE = NW * 8;   // 16 rows/step
        char* wstage = S.stage[w];
        const int wrow0 = r0 + w * 8;
        const int iters = (r1 > wrow0) ? ((r1 - wrow0 + STRIDE - 1) / STRIDE) : 0;
        #pragma unroll
        for (int j = 0; j < RS - 1; j++) {
            if (j < iters) fill32(wstage + j * SLICE, x, wrow0 + j * STRIDE, r1, lane);
            __pipeline_commit();
        }
        int slot = 0;
        for (int j = 0; j < iters; j++) {
            __pipeline_wait_prior(RS - 2);
            int jn = j + RS - 1;
            int sn = slot + RS - 1; if (sn >= RS) sn -= RS;
            if (jn < iters) fill32(wstage + sn * SLICE, x, wrow0 + jn * STRIDE, r1, lane);
            __pipeline_commit();
            {
                const int row = wrow0 + j * STRIDE + q;
                const bool act = (row < r1);
                const float4* p4 = (const float4*)(wstage + slot * SLICE + q * 256 + ql * 64);
                float4 v0 = p4[0], v1 = p4[1], v2 = p4[2], v3 = p4[3];
                if (act) {   // fp16 copy for steps 1-4
                    union { uint4 u; __half2 h[4]; } pk0, pk1;
                    pk0.h[0] = __floats2half2_rn(v0.x, v0.y);
                    pk0.h[1] = __floats2half2_rn(v0.z, v0.w);
                    pk0.h[2] = __floats2half2_rn(v1.x, v1.y);
                    pk0.h[3] = __floats2half2_rn(v1.z, v1.w);
                    pk1.h[0] = __floats2half2_rn(v2.x, v2.y);
                    pk1.h[1] = __floats2half2_rn(v2.z, v2.w);
                    pk1.h[2] = __floats2half2_rn(v3.x, v3.y);
                    pk1.h[3] = __floats2half2_rn(v3.z, v3.w);
                    __stcs(&d_xh[(size_t)row * 8 + 2 * ql],     pk0.u);
                    __stcs(&d_xh[(size_t)row * 8 + 2 * ql + 1], pk1.u);
                }
                float p  = dot16(v0, v1, v2, v3, q0, q1, q2, q3);
                float n2 = dot16(v0, v1, v2, v3, v0, v1, v2, v3);
                p  += __shfl_xor_sync(0xffffffffu, p, 1);
                n2 += __shfl_xor_sync(0xffffffffu, n2, 1);
                p  += __shfl_xor_sync(0xffffffffu, p, 2);
                n2 += __shfl_xor_sync(0xffffffffu, n2, 2);
                if (act) {
                    mn = fmaxf(mn, n2);
                    if (p > m) {
                        float sc = __expf(m - p);
                        s *= sc;
                        R0.x *= sc; R0.y *= sc; R0.z *= sc; R0.w *= sc;
                        R1.x *= sc; R1.y *= sc; R1.z *= sc; R1.w *= sc;
                        R2.x *= sc; R2.y *= sc; R2.z *= sc; R2.w *= sc;
                        R3.x *= sc; R3.y *= sc; R3.z *= sc; R3.w *= sc;
                        m = p;
                    }
                    acc16(s, R0, R1, R2, R3, __expf(p - m), v0, v1, v2, v3);
                }
            }
            __syncwarp();
            slot++; if (slot == RS) slot = 0;
        }
        __pipeline_wait_prior(0);
    }

    // combine NQ quad partials -> r, mn
    if (ql == 0) { S.s_rm[qd] = m; S.s_rs[qd] = s; S.s_rmn[qd] = mn; }
    ((float4*)S.s_rR[qd])[4 * ql]     = R0;
    ((float4*)S.s_rR[qd])[4 * ql + 1] = R1;
    ((float4*)S.s_rR[qd])[4 * ql + 2] = R2;
    ((float4*)S.s_rR[qd])[4 * ql + 3] = R3;
    __syncthreads();
    {
        float Mx = -FLT_MAX;
        #pragma unroll
        for (int p = 0; p < NQ; p++) Mx = fmaxf(Mx, S.s_rm[p]);
        float st = 0.0f, Rk = 0.0f;
        #pragma unroll
        for (int p = 0; p < NQ; p++) {
            float wq = __expf(S.s_rm[p] - Mx);
            st += wq * S.s_rs[p];
            Rk += wq * S.s_rR[p][t];
        }
        d_sr[g * 64 + t] = Rk / fmaxf(st, 1e-16f);
        if (t == 0) {
            float mnx = 0.0f;
            #pragma unroll
            for (int p = 0; p < NQ; p++) mnx = fmaxf(mnx, S.s_rmn[p]);
            d_smn[g] = mnx;
        }
    }
}

// ================= K1: steps 1-4 (fp16, fixed shift) + MLP =================
struct SmemK1 {
    char  stage[NW][6 * 1024];  // fp16 ring: 6 slots x 8 rows
    float s_rR[NQ][64];
    float s_act[128];           // [h | r]
    float s_c[64];
    float s_g[256];             // MLP hidden
    float s_rs[NQ];
    float s_h2[NW];
    float s_M[1];
    float s_mn[1];
};

__device__ __forceinline__ void fill16(char* slot, int srow0, int r1, int lane) {
    int row = srow0 + (lane >> 2);
    row = min(row, r1 - 1);
    const char* g = (const char*)(&d_xh[(size_t)row * 8]) + (lane & 3) * 32;
    char* sdst = slot + (lane >> 2) * 128 + (lane & 3) * 32;
    __pipeline_memcpy_async(sdst,      g,      16);
    __pipeline_memcpy_async(sdst + 16, g + 16, 16);
}

__global__ __launch_bounds__(NTHR, 10)
void steps14_kernel(const float* __restrict__ b1, const float* __restrict__ b2,
                    float* __restrict__ out, int n) {
    extern __shared__ char smraw[];
    SmemK1& S = *(SmemK1*)smraw;

    const int t    = threadIdx.x;
    const int g    = blockIdx.x;
    const int w    = t >> 5;
    const int lane = t & 31;
    const int q    = lane >> 2;
    const int ql   = t & 3;
    const int qd   = t >> 2;
    char* wstage   = S.stage[w];

    S.s_act[t]      = d_sh[g * 64 + t];
    S.s_act[64 + t] = d_sr[g * 64 + t];
    S.s_c[t]        = d_sc[g * 64 + t];
    if (t == 0) S.s_mn[0] = d_smn[g];
    int r0 = d_seg[g];
    int r1 = d_seg[g + 1];
    r0 = min(max(r0, 0), n);
    r1 = min(max(r1, r0), n);
    __syncthreads();

    for (int step = 1; step < 5; step++) {
        // ---- LSTM: thread t owns gates i,f,g,o for cell k=t ----
        {
            float ai = d_bsum[t], af = d_bsum[t + 64];
            float ag = d_bsum[t + 128], ao = d_bsum[t + 192];
            const float4* a0 = (const float4*)S.s_act;
            #pragma unroll 8
            for (int k4 = 0; k4 < 32; k4++) {
                float4 v  = a0[k4];
                float4 wi = d_WL[k4 * 256 + t];
                float4 wf = d_WL[k4 * 256 + t + 64];
                float4 wg = d_WL[k4 * 256 + t + 128];
                float4 wo = d_WL[k4 * 256 + t + 192];
                ai += wi.x * v.x + wi.y * v.y + wi.z * v.z + wi.w * v.w;
                af += wf.x * v.x + wf.y * v.y + wf.z * v.z + wf.w * v.w;
                ag += wg.x * v.x + wg.y * v.y + wg.z * v.z + wg.w * v.w;
                ao += wo.x * v.x + wo.y * v.y + wo.z * v.z + wo.w * v.w;
            }
            __syncthreads();
            float gi = sigmoidf_(ai);
            float gf = sigmoidf_(af);
            float gg = tanhf(ag);
            float go = sigmoidf_(ao);
            float cc = gf * S.s_c[t] + gi * gg;
            S.s_c[t] = cc;
            float hv = go * tanhf(cc);
            S.s_act[t] = hv;
            float h2 = hv * hv;
            #pragma unroll
            for (int msk = 16; msk >= 1; msk >>= 1)
                h2 += __shfl_xor_sync(0xffffffffu, h2, msk);
            if (lane == 0) S.s_h2[w] = h2;
        }
        __syncthreads();
        if (t == 0)
            S.s_M[0] = sqrtf((S.s_h2[0] + S.s_h2[1]) * S.s_mn[0]);
        __syncthreads();

        const float4 q0 = ((const float4*)S.s_act)[4 * ql];
        const float4 q1 = ((const float4*)S.s_act)[4 * ql + 1];
        const float4 q2 = ((const float4*)S.s_act)[4 * ql + 2];
        const float4 q3 = ((const float4*)S.s_act)[4 * ql + 3];
        const float M = S.s_M[0];
        float s = 0.0f;
        float4 R0 = make_float4(0.f, 0.f, 0.f, 0.f);
        float4 R1 = R0, R2 = R0, R3 = R0;

        {
            constexpr int RS = 6, SLICE = 1024, STRIDE = NW * 8;   // 16 rows/step
            const int wrow0 = r0 + w * 8;
            const int iters = (r1 > wrow0) ? ((r1 - wrow0 + STRIDE - 1) / STRIDE) : 0;
            #pragma unroll
            for (int j = 0; j < RS - 1; j++) {
                if (j < iters) fill16(wstage + j * SLICE, wrow0 + j * STRIDE, r1, lane);
                __pipeline_commit();
            }
            int slot = 0;
            for (int j = 0; j < iters; j++) {
                __pipeline_wait_prior(RS - 2);
                int jn = j + RS - 1;
                int sn = slot + RS - 1; if (sn >= RS) sn -= RS;
                if (jn < iters) fill16(wstage + sn * SLICE, wrow0 + jn * STRIDE, r1, lane);
                __pipeline_commit();
                {
                    const int row = wrow0 + j * STRIDE + q;
                    const uint4* p4 = (const uint4*)(wstage + slot * SLICE + q * 128 + ql * 32);
                    union { uint4 u; __half2 h[4]; } pk0, pk1;
                    pk0.u = p4[0];
                    pk1.u = p4[1];
                    float2 f;
                    float4 v0, v1, v2, v3;
                    f = __half22float2(pk0.h[0]); v0.x = f.x; v0.y = f.y;
                    f = __half22float2(pk0.h[1]); v0.z = f.x; v0.w = f.y;
                    f = __half22float2(pk0.h[2]); v1.x = f.x; v1.y = f.y;
                    f = __half22float2(pk0.h[3]); v1.z = f.x; v1.w = f.y;
                    f = __half22float2(pk1.h[0]); v2.x = f.x; v2.y = f.y;
                    f = __half22float2(pk1.h[1]); v2.z = f.x; v2.w = f.y;
                    f = __half22float2(pk1.h[2]); v3.x = f.x; v3.y = f.y;
                    f = __half22float2(pk1.h[3]); v3.z = f.x; v3.w = f.y;
                    float p = dot16(v0, v1, v2, v3, q0, q1, q2, q3);
                    p += __shfl_xor_sync(0xffffffffu, p, 1);
                    p += __shfl_xor_sync(0xffffffffu, p, 2);
                    float d = (row < r1) ? __expf(p - M) : 0.0f;
                    acc16(s, R0, R1, R2, R3, d, v0, v1, v2, v3);
                }
                __syncwarp();
                slot++; if (slot == RS) slot = 0;
            }
            __pipeline_wait_prior(0);
        }

        // combine (all quads share the same shift M)
        if (ql == 0) S.s_rs[qd] = s;
        ((float4*)S.s_rR[qd])[4 * ql]     = R0;
        ((float4*)S.s_rR[qd])[4 * ql + 1] = R1;
        ((float4*)S.s_rR[qd])[4 * ql + 2] = R2;
        ((float4*)S.s_rR[qd])[4 * ql + 3] = R3;
        __syncthreads();
        {
            float st = 0.0f, Rk = 0.0f;
            #pragma unroll
            for (int p = 0; p < NQ; p++) {
                st += S.s_rs[p];
                Rk += S.s_rR[p][t];
            }
            float r = Rk / fmaxf(st, 1e-16f);
            __syncthreads();
            S.s_act[64 + t] = r;
        }
        __syncthreads();
    }

    // ---- final MLP: 128 -> 256 (relu) -> 128 ----
    {
        float a0 = b1[t], a1 = b1[t + 64], a2 = b1[t + 128], a3 = b1[t + 192];
        const float4* a = (const float4*)S.s_act;
        #pragma unroll 8
        for (int k4 = 0; k4 < 32; k4++) {
            float4 v  = a[k4];
            float4 w0 = d_W1p[k4 * 256 + t];
            float4 w1 = d_W1p[k4 * 256 + t + 64];
            float4 w2 = d_W1p[k4 * 256 + t + 128];
            float4 w3 = d_W1p[k4 * 256 + t + 192];
            a0 += w0.x * v.x + w0.y * v.y + w0.z * v.z + w0.w * v.w;
            a1 += w1.x * v.x + w1.y * v.y + w1.z * v.z + w1.w * v.w;
            a2 += w2.x * v.x + w2.y * v.y + w2.z * v.z + w2.w * v.w;
            a3 += w3.x * v.x + w3.y * v.y + w3.z * v.z + w3.w * v.w;
        }
        S.s_g[t]       = fmaxf(a0, 0.0f);
        S.s_g[t + 64]  = fmaxf(a1, 0.0f);
        S.s_g[t + 128] = fmaxf(a2, 0.0f);
        S.s_g[t + 192] = fmaxf(a3, 0.0f);
    }
    __syncthreads();
    {
        float o0 = b2[t], o1 = b2[t + 64];
        const float4* hv = (const float4*)S.s_g;
        #pragma unroll 8
        for (int k4 = 0; k4 < 64; k4++) {
            float4 v  = hv[k4];
            float4 w0 = d_W2p[k4 * 128 + t];
            float4 w1 = d_W2p[k4 * 128 + t + 64];
            o0 += w0.x * v.x + w0.y * v.y + w0.z * v.z + w0.w * v.w;
            o1 += w1.x * v.x + w1.y * v.y + w1.z * v.z + w1.w * v.w;
        }
        out[(size_t)g * 128 + t]      = o0;
        out[(size_t)g * 128 + t + 64] = o1;
    }
}

extern "C" void kernel_launch(void* const* d_in, const int* in_sizes, int n_in,
                              void* d_out, int out_size) {
    const float* x     = (const float*)d_in[0];
    const int*   batch = (const int*)d_in[1];     // int32 (JAX x64 disabled)
    const float* Wih   = (const float*)d_in[2];
    const float* Whh   = (const float*)d_in[3];
    const float* bih   = (const float*)d_in[4];
    const float* bhh   = (const float*)d_in[5];
    const float* W1    = (const float*)d_in[6];
    const float* b1    = (const float*)d_in[7];
    const float* W2    = (const float*)d_in[8];
    const float* b2    = (const float*)d_in[9];

    int n = in_sizes[0] / HDIM;   // number of nodes

    static_assert(sizeof(SmemK0) <= 28 * 1024, "K0 smem too big for occ 8");
    static_assert(sizeof(SmemK1) <= 22 * 1024, "K1 smem too big for occ 10");
    cudaFuncSetAttribute(step0_kernel,   cudaFuncAttributeMaxDynamicSharedMemorySize,
                         (int)sizeof(SmemK0));
    cudaFuncSetAttribute(steps14_kernel, cudaFuncAttributeMaxDynamicSharedMemorySize,
                         (int)sizeof(SmemK1));

    prep_kernel<<<(n + 511) / 512, 512>>>(batch, n, Wih, Whh, bih, bhh, W1, W2);
    step0_kernel<<<CTAS, NTHR, sizeof(SmemK0)>>>(x, n);
    steps14_kernel<<<CTAS, NTHR, sizeof(SmemK1)>>>(b1, b2, (float*)d_out, n);
}